// round 13
// baseline (speedup 1.0000x reference)
#include <cuda_runtime.h>

#define NPIX (2048*2048)
#define NB   256
#define NRC  12          // 4 regions * 3 channels
#define FINE 512         // fine bins: 2*idx + (cdf_bin != idx)
#define GRID1 296        // exactly 2 blocks/SM on 148 SMs
#define THR1  512
#define SMEM1 (NRC*FINE*8 + NRC*NB*4)   // 49152 + 12288 = 61440 bytes
#define M40 ((1ULL<<40)-1ULL)

// ---------------- global accumulators (zero-init; finalize re-zeros each launch) -----
static __device__ unsigned long long g_fine[NRC*FINE];
static __device__ unsigned           g_tar [NRC*NB];
static __device__ int                g_ctr;

// 3-bit region codes (region+1; 0 = none) packed LSB-first per label 0..18.
// regions: 0=face, 1=hair, 2=eyeL, 3=eyeR
// src face labels {1,7,8,10,11,14}; tar face labels drop 11 (the reference "bug" adds
// mask_A==11 to the tar face mask separately).
#define CODEBASE ( (1ULL<<3) | (3ULL<<6) | (4ULL<<9) | (3ULL<<12) | (4ULL<<15) \
                 | (1ULL<<21) | (1ULL<<24) | (1ULL<<30) | (1ULL<<42) | (2ULL<<51) )
#define SRCMAP (CODEBASE | (1ULL<<33))   // label 11 -> face (src only)
#define TARMAP (CODEBASE)                // label 11 -> none (tar)

__device__ __forceinline__ float dn(float x) {
    // exactly: clip((x+1)*0.5, 0, 1) * 255, add->mul order, no fma contraction
    return __fmul_rn(__saturatef(__fmul_rn(__fadd_rn(x, 1.0f), 0.5f)), 255.0f);
}

__device__ __forceinline__ void px(int la, int lb,
    float f0, float f1, float f2, float r0, float r1, float r2,
    unsigned long long* s_fine, unsigned* s_tar)
{
    const float CST = (float)(256.0 / 255.0);
    int rs = (int)((SRCMAP >> (3*la)) & 7ULL) - 1;
    int rt = (int)((TARMAP >> (3*lb)) & 7ULL) - 1;
    int extra = (la == 11) ? 1 : 0;

    // ---- src: 1 packed u64 atomic per channel (count<<40 | frac*2^20) ----
    if (rs >= 0) {
        float vv[3] = {dn(f0), dn(f1), dn(f2)};
        unsigned long long* base = s_fine + rs*3*FINE;
        #pragma unroll
        for (int c = 0; c < 3; c++) {
            float v  = vv[c];
            int idx  = (int)v;                       // floor (v>=0)
            int cb   = (int)__fmul_rn(v, CST);       // floor(v*256/255), bit-exact w/ ref
            if (cb > 255) cb = 255;
            unsigned un = (unsigned)((v - (float)idx) * 1048576.0f + 0.5f);
            int f = 2*idx + ((cb > idx) ? 1 : 0);
            atomicAdd(base + c*FINE + f, (1ULL << 40) + (unsigned long long)un);
        }
    }

    // ---- tar: unified primary (face-mask path OR region path), rare secondary ----
    int fm = ((rt == 0) ? 1 : 0) + extra;            // face mask value (0,1,2)
    if (fm | (rt > 0)) {
        float vv[3] = {dn(r0), dn(r1), dn(r2)};
        int base = fm ? 0 : rt*3*NB;                 // face table rows are rc 0..2
        float m  = (float)fm;
        #pragma unroll
        for (int c = 0; c < 3; c++) {
            float u = fm ? __fmul_rn(vv[c], m) : vv[c];
            int bb = (int)__fmul_rn(u, CST);
            if (bb > 255) bb = 255;
            atomicAdd(&s_tar[base + c*NB + bb], 1u);
        }
        // double-contribution: mask_A==11 (face extra) AND tar pixel in hair/eye
        if (extra & (rt > 0)) {
            #pragma unroll
            for (int c = 0; c < 3; c++) {
                int bb = (int)__fmul_rn(vv[c], CST);
                if (bb > 255) bb = 255;
                atomicAdd(&s_tar[rt*3*NB + c*NB + bb], 1u);
            }
        }
    }
}

// =================== single fused kernel: histogram pass + finalize ==================
__global__ void __launch_bounds__(THR1, 2) hm_all(
    const float4* __restrict__ fa, const float4* __restrict__ rb,
    const int4* __restrict__ ma, const int4* __restrict__ mb,
    float* __restrict__ out)
{
    extern __shared__ unsigned char smem[];
    unsigned long long* s_fine = (unsigned long long*)smem;                     // [NRC*FINE]
    unsigned* s_tar = (unsigned*)(smem + NRC*FINE*sizeof(unsigned long long));  // [NRC*NB]

    for (int i = threadIdx.x; i < NRC*FINE; i += THR1) s_fine[i] = 0ULL;
    for (int i = threadIdx.x; i < NRC*NB;  i += THR1) s_tar[i]  = 0u;
    __syncthreads();

    const int n4 = NPIX / 4;
    const int stride = gridDim.x * blockDim.x;
    for (int g = blockIdx.x * blockDim.x + threadIdx.x; g < n4; g += stride) {
        int4   a  = ma[g];
        int4   b  = mb[g];
        float4 f0 = fa[g];
        float4 f1 = fa[g +     n4];
        float4 f2 = fa[g + 2 * n4];
        float4 r0 = rb[g];
        float4 r1 = rb[g +     n4];
        float4 r2 = rb[g + 2 * n4];
        px(a.x, b.x, f0.x, f1.x, f2.x, r0.x, r1.x, r2.x, s_fine, s_tar);
        px(a.y, b.y, f0.y, f1.y, f2.y, r0.y, r1.y, r2.y, s_fine, s_tar);
        px(a.z, b.z, f0.z, f1.z, f2.z, r0.z, r1.z, r2.z, s_fine, s_tar);
        px(a.w, b.w, f0.w, f1.w, f2.w, r0.w, r1.w, r2.w, s_fine, s_tar);
    }
    __syncthreads();

    // flush: global atomics into small tables (spread addresses -> L2-pipelined)
    for (int i = threadIdx.x; i < NRC*FINE; i += THR1) {
        unsigned long long v = s_fine[i];
        if (v) atomicAdd(&g_fine[i], v);
    }
    for (int i = threadIdx.x; i < NRC*NB; i += THR1) {
        unsigned v = s_tar[i];
        if (v) atomicAdd(&g_tar[i], v);
    }
    __threadfence();
    __syncthreads();

    __shared__ int isLast;
    if (threadIdx.x == 0)
        isLast = (atomicAdd(&g_ctr, 1) == (int)gridDim.x - 1);
    __syncthreads();
    if (!isLast) return;
    __threadfence();   // acquire: all other blocks' flushes visible

    // ---------------- finalize (last block only): 12 warps <-> 12 region-channels ----
    // reuse dynamic smem:
    float*  acb  = (float*) smem;                    // 12*256*4 = 12288
    unsigned* cntb = (unsigned*)(smem + 12288);      // 12*256*4 = 12288
    double* Fb   = (double*)(smem + 24576);          // 12*256*8 = 24576 (ends 49152)
    double* s_ls = (double*)(smem + 49152);          // 12 doubles

    const int w = threadIdx.x >> 5;   // warp = rc
    const int L = threadIdx.x & 31;
    const unsigned FULL = 0xffffffffu;

    if (w < NRC) {
        const int rc = w;

        // ---- src fine bins: counts, frac sums, cdf-histogram ----
        unsigned hk[8];
        unsigned lsum = 0, prev_c1 = 0;
        #pragma unroll
        for (int k = 0; k < 8; k++) {
            int e = L*8 + k;
            unsigned long long a0 = __ldcg(&g_fine[rc*FINE + 2*e]);
            unsigned long long a1 = __ldcg(&g_fine[rc*FINE + 2*e + 1]);
            g_fine[rc*FINE + 2*e]     = 0ULL;       // reset for next graph replay
            g_fine[rc*FINE + 2*e + 1] = 0ULL;
            unsigned c0 = (unsigned)(a0 >> 40), c1 = (unsigned)(a1 >> 40);
            cntb[w*NB + e] = c0 + c1;
            Fb[w*NB + e]   = (double)((a0 & M40) + (a1 & M40));
            unsigned h = c0 + (k ? prev_c1 : 0u);   // hist[e] = fine[2e] + fine[2e-1]
            prev_c1 = c1;
            hk[k] = h;
            lsum += h;
        }
        unsigned nb = __shfl_up_sync(FULL, prev_c1, 1);  // lane L-1's bin 2e+1 (k=7)
        if (L > 0) { hk[0] += nb; lsum += nb; }

        // total src count (butterfly reduce)
        unsigned tot_s = lsum;
        #pragma unroll
        for (int off = 16; off; off >>= 1) tot_s += __shfl_xor_sync(FULL, tot_s, off);
        float den_s = fmaxf((float)tot_s, 1.0f);

        // divided-value scan: dc
        float dck[8];
        {
            float r = 0.0f;
            #pragma unroll
            for (int k = 0; k < 8; k++) { r += (float)hk[k] / den_s; dck[k] = r; }
            float lt = r, x = r;
            #pragma unroll
            for (int off = 1; off < 32; off <<= 1) {
                float y = __shfl_up_sync(FULL, x, off);
                if (L >= off) x += y;
            }
            float excl = x - lt;
            #pragma unroll
            for (int k = 0; k < 8; k++) dck[k] += excl;
        }

        // ---- tar histogram -> ac (staged to smem for binary search) ----
        unsigned tk[8], tsum = 0;
        #pragma unroll
        for (int k = 0; k < 8; k++) {
            int e = L*8 + k;
            tk[k] = __ldcg(&g_tar[rc*NB + e]);
            g_tar[rc*NB + e] = 0u;                  // reset for next graph replay
            tsum += tk[k];
        }
        unsigned tot_t = tsum;
        #pragma unroll
        for (int off = 16; off; off >>= 1) tot_t += __shfl_xor_sync(FULL, tot_t, off);
        float den_t = fmaxf((float)tot_t, 1.0f);
        {
            float r = 0.0f; float ack[8];
            #pragma unroll
            for (int k = 0; k < 8; k++) { r += (float)tk[k] / den_t; ack[k] = r; }
            float lt = r, x = r;
            #pragma unroll
            for (int off = 1; off < 32; off <<= 1) {
                float y = __shfl_up_sync(FULL, x, off);
                if (L >= off) x += y;
            }
            float excl = x - lt;
            #pragma unroll
            for (int k = 0; k < 8; k++) acb[w*NB + L*8 + k] = ack[k] + excl;
        }
        __syncwarp();

        float ac0 = acb[w*NB], ac255 = acb[w*NB + NB - 1];

        // ---- transfer table (binary search == reference first-match) + loss ----
        double acc = 0.0;
        #pragma unroll
        for (int k = 0; k < 8; k++) {
            int e = L*8 + k;
            float d = dck[k];
            int t;
            if (e == 0)            t = 0;
            else if (e == NB - 1)  t = NB - 1;
            else if (d < ac0 || d > ac255) t = e;   // no j satisfies both conditions
            else {
                // first j in [1,255] with ac[j] >= d  (then ac[j-1] <= d by minimality)
                int lo = 1, hi = NB - 1;
                while (lo < hi) {
                    int mid = (lo + hi) >> 1;
                    if (acb[w*NB + mid] >= d) hi = mid; else lo = mid + 1;
                }
                t = lo;
            }
            unsigned cnt = cntb[w*NB + e];
            double s  = (double)cnt * (double)e + Fb[w*NB + e] * (1.0 / 1048576.0);
            double cT = (double)cnt * (double)t;
            acc += (t <= e) ? (s - cT) : (cT - s);  // sign fixed: v in [e, e+1)
        }
        #pragma unroll
        for (int off = 16; off; off >>= 1) acc += __shfl_down_sync(FULL, acc, off);
        if (L == 0) s_ls[w] = acc;
    }
    __syncthreads();

    if (threadIdx.x == 0) {
        double tot = 0.0;
        #pragma unroll
        for (int r = 0; r < NRC; r++) tot += s_ls[r];
        out[0] = (float)(0.1 * tot / (3.0 * (double)NPIX));
        g_ctr = 0;                                  // reset for next graph replay
    }
}

extern "C" void kernel_launch(void* const* d_in, const int* in_sizes, int n_in,
                              void* d_out, int out_size)
{
    const float4* fa = (const float4*)d_in[0];
    const float4* rb = (const float4*)d_in[1];
    const int4*   ma = (const int4*)d_in[2];
    const int4*   mb = (const int4*)d_in[3];

    cudaFuncSetAttribute(hm_all, cudaFuncAttributeMaxDynamicSharedMemorySize, SMEM1);
    hm_all<<<GRID1, THR1, SMEM1>>>(fa, rb, ma, mb, (float*)d_out);
}

// round 17
// speedup vs baseline: 1.7526x; 1.7526x over previous
#include <cuda_runtime.h>

#define NPIX (2048*2048)
#define NB   256
#define NRC  12          // 4 regions * 3 channels
#define FINE 512         // fine bins: 2*idx + (cdf_bin != idx)
#define GRID1 296        // exactly 2 blocks/SM on 148 SMs
#define THR1  512
#define SMEM1 (NRC*FINE*4 + NRC*NB*4 + NRC*NB*4 + 128)   // 24576+12288+12288+128 = 49280
#define FSCALE 262144.0f          // 2^18 frac quantization
#define FINV   (1.0 / 262144.0)

// ---------------- global accumulators (zero-init; finalize re-zeros each launch) -----
static __device__ unsigned           g_cnt [NRC*FINE];   // fine-bin counts
static __device__ unsigned long long g_frac[NRC*NB];     // per-idx frac sums (2^-18 units)
static __device__ unsigned           g_tar [NRC*NB];
static __device__ int                g_ctr;

// 3-bit region codes (region+1; 0 = none) packed LSB-first per label 0..18.
// regions: 0=face, 1=hair, 2=eyeL, 3=eyeR
// src face labels {1,7,8,10,11,14}; tar face labels drop 11 (the reference "bug" adds
// mask_A==11 to the tar face mask separately).
#define CODEBASE ( (1ULL<<3) | (3ULL<<6) | (4ULL<<9) | (3ULL<<12) | (4ULL<<15) \
                 | (1ULL<<21) | (1ULL<<24) | (1ULL<<30) | (1ULL<<42) | (2ULL<<51) )
#define SRCMAP (CODEBASE | (1ULL<<33))   // label 11 -> face (src only)
#define TARMAP (CODEBASE)                // label 11 -> none (tar)

__device__ __forceinline__ float dn(float x) {
    // exactly: clip((x+1)*0.5, 0, 1) * 255, add->mul order, no fma contraction
    return __fmul_rn(__saturatef(__fmul_rn(__fadd_rn(x, 1.0f), 0.5f)), 255.0f);
}

__device__ __forceinline__ void px(int la, int lb,
    float f0, float f1, float f2, float r0, float r1, float r2,
    unsigned* s_cnt, unsigned* s_frac, unsigned* s_tar)
{
    const float CST = (float)(256.0 / 255.0);
    int rs = (int)((SRCMAP >> (3*la)) & 7ULL) - 1;
    int rt = (int)((TARMAP >> (3*lb)) & 7ULL) - 1;
    int extra = (la == 11) ? 1 : 0;

    // ---- src: 2 u32 atomics per channel (fine-bin count + per-idx frac sum) ----
    if (rs >= 0) {
        float vv[3] = {dn(f0), dn(f1), dn(f2)};
        unsigned* cbase = s_cnt  + rs*3*FINE;
        unsigned* fbase = s_frac + rs*3*NB;
        #pragma unroll
        for (int c = 0; c < 3; c++) {
            float v  = vv[c];
            int idx  = (int)v;                       // floor (v>=0)
            int cb   = (int)__fmul_rn(v, CST);       // floor(v*256/255), bit-exact w/ ref
            if (cb > 255) cb = 255;
            unsigned un = (unsigned)((v - (float)idx) * FSCALE + 0.5f);
            int f = 2*idx + ((cb > idx) ? 1 : 0);
            atomicAdd(cbase + c*FINE + f, 1u);
            atomicAdd(fbase + c*NB + idx, un);
        }
    }

    // ---- tar: unified primary (face-mask path OR region path), rare secondary ----
    int fm = ((rt == 0) ? 1 : 0) + extra;            // face mask value (0,1,2)
    if (fm | (rt > 0)) {
        float vv[3] = {dn(r0), dn(r1), dn(r2)};
        int base = fm ? 0 : rt*3*NB;                 // face table rows are rc 0..2
        float m  = (float)fm;
        #pragma unroll
        for (int c = 0; c < 3; c++) {
            float u = fm ? __fmul_rn(vv[c], m) : vv[c];
            int bb = (int)__fmul_rn(u, CST);
            if (bb > 255) bb = 255;
            atomicAdd(&s_tar[base + c*NB + bb], 1u);
        }
        // double-contribution: mask_A==11 (face extra) AND tar pixel in hair/eye
        if (extra & (rt > 0)) {
            #pragma unroll
            for (int c = 0; c < 3; c++) {
                int bb = (int)__fmul_rn(vv[c], CST);
                if (bb > 255) bb = 255;
                atomicAdd(&s_tar[rt*3*NB + c*NB + bb], 1u);
            }
        }
    }
}

// =================== single fused kernel: histogram pass + finalize ==================
__global__ void __launch_bounds__(THR1, 2) hm_all(
    const float4* __restrict__ fa, const float4* __restrict__ rb,
    const int4* __restrict__ ma, const int4* __restrict__ mb,
    float* __restrict__ out)
{
    extern __shared__ unsigned char smem[];
    unsigned* s_cnt  = (unsigned*)smem;                          // [NRC*FINE] 24576 B
    unsigned* s_frac = (unsigned*)(smem + NRC*FINE*4);           // [NRC*NB]  12288 B
    unsigned* s_tar  = (unsigned*)(smem + NRC*FINE*4 + NRC*NB*4);// [NRC*NB]  12288 B

    for (int i = threadIdx.x; i < NRC*FINE; i += THR1) s_cnt[i] = 0u;
    for (int i = threadIdx.x; i < NRC*NB;  i += THR1) { s_frac[i] = 0u; s_tar[i] = 0u; }
    __syncthreads();

    const int n4 = NPIX / 4;
    const int stride = gridDim.x * blockDim.x;
    for (int g = blockIdx.x * blockDim.x + threadIdx.x; g < n4; g += stride) {
        int4   a  = ma[g];
        int4   b  = mb[g];
        float4 f0 = fa[g];
        float4 f1 = fa[g +     n4];
        float4 f2 = fa[g + 2 * n4];
        float4 r0 = rb[g];
        float4 r1 = rb[g +     n4];
        float4 r2 = rb[g + 2 * n4];
        px(a.x, b.x, f0.x, f1.x, f2.x, r0.x, r1.x, r2.x, s_cnt, s_frac, s_tar);
        px(a.y, b.y, f0.y, f1.y, f2.y, r0.y, r1.y, r2.y, s_cnt, s_frac, s_tar);
        px(a.z, b.z, f0.z, f1.z, f2.z, r0.z, r1.z, r2.z, s_cnt, s_frac, s_tar);
        px(a.w, b.w, f0.w, f1.w, f2.w, r0.w, r1.w, r2.w, s_cnt, s_frac, s_tar);
    }
    __syncthreads();

    // flush: global atomics into small tables (spread addresses -> L2-pipelined)
    for (int i = threadIdx.x; i < NRC*FINE; i += THR1) {
        unsigned v = s_cnt[i];
        if (v) atomicAdd(&g_cnt[i], v);
    }
    for (int i = threadIdx.x; i < NRC*NB; i += THR1) {
        unsigned v = s_frac[i];
        if (v) atomicAdd(&g_frac[i], (unsigned long long)v);
        unsigned t = s_tar[i];
        if (t) atomicAdd(&g_tar[i], t);
    }
    __threadfence();
    __syncthreads();

    __shared__ int isLast;
    if (threadIdx.x == 0)
        isLast = (atomicAdd(&g_ctr, 1) == (int)gridDim.x - 1);
    __syncthreads();
    if (!isLast) return;
    __threadfence();   // acquire: all other blocks' flushes visible

    // ---------------- finalize (last block only): 12 warps <-> 12 region-channels ----
    // reuse dynamic smem:
    float*  acb  = (float*) smem;                    // 12*256*4 = 12288
    unsigned* cntb = (unsigned*)(smem + 12288);      // 12*256*4 = 12288
    double* Fb   = (double*)(smem + 24576);          // 12*256*8 = 24576 (ends 49152)
    double* s_ls = (double*)(smem + 49152);          // 12 doubles

    const int w = threadIdx.x >> 5;   // warp = rc
    const int L = threadIdx.x & 31;
    const unsigned FULL = 0xffffffffu;

    if (w < NRC) {
        const int rc = w;

        // ---- src fine bins: counts, frac sums, cdf-histogram ----
        unsigned hk[8];
        unsigned lsum = 0, prev_c1 = 0;
        #pragma unroll
        for (int k = 0; k < 8; k++) {
            int e = L*8 + k;
            unsigned c0 = __ldcg(&g_cnt[rc*FINE + 2*e]);
            unsigned c1 = __ldcg(&g_cnt[rc*FINE + 2*e + 1]);
            g_cnt[rc*FINE + 2*e]     = 0u;          // reset for next graph replay
            g_cnt[rc*FINE + 2*e + 1] = 0u;
            unsigned long long fs = __ldcg(&g_frac[rc*NB + e]);
            g_frac[rc*NB + e] = 0ULL;               // reset for next graph replay
            cntb[w*NB + e] = c0 + c1;
            Fb[w*NB + e]   = (double)fs;
            unsigned h = c0 + (k ? prev_c1 : 0u);   // hist[e] = fine[2e] + fine[2e-1]
            prev_c1 = c1;
            hk[k] = h;
            lsum += h;
        }
        unsigned nb = __shfl_up_sync(FULL, prev_c1, 1);  // lane L-1's bin 2e+1 (k=7)
        if (L > 0) { hk[0] += nb; lsum += nb; }

        // total src count (butterfly reduce)
        unsigned tot_s = lsum;
        #pragma unroll
        for (int off = 16; off; off >>= 1) tot_s += __shfl_xor_sync(FULL, tot_s, off);
        float den_s = fmaxf((float)tot_s, 1.0f);

        // divided-value scan: dc
        float dck[8];
        {
            float r = 0.0f;
            #pragma unroll
            for (int k = 0; k < 8; k++) { r += (float)hk[k] / den_s; dck[k] = r; }
            float lt = r, x = r;
            #pragma unroll
            for (int off = 1; off < 32; off <<= 1) {
                float y = __shfl_up_sync(FULL, x, off);
                if (L >= off) x += y;
            }
            float excl = x - lt;
            #pragma unroll
            for (int k = 0; k < 8; k++) dck[k] += excl;
        }

        // ---- tar histogram -> ac (staged to smem for binary search) ----
        unsigned tk[8], tsum = 0;
        #pragma unroll
        for (int k = 0; k < 8; k++) {
            int e = L*8 + k;
            tk[k] = __ldcg(&g_tar[rc*NB + e]);
            g_tar[rc*NB + e] = 0u;                  // reset for next graph replay
            tsum += tk[k];
        }
        unsigned tot_t = tsum;
        #pragma unroll
        for (int off = 16; off; off >>= 1) tot_t += __shfl_xor_sync(FULL, tot_t, off);
        float den_t = fmaxf((float)tot_t, 1.0f);
        {
            float r = 0.0f; float ack[8];
            #pragma unroll
            for (int k = 0; k < 8; k++) { r += (float)tk[k] / den_t; ack[k] = r; }
            float lt = r, x = r;
            #pragma unroll
            for (int off = 1; off < 32; off <<= 1) {
                float y = __shfl_up_sync(FULL, x, off);
                if (L >= off) x += y;
            }
            float excl = x - lt;
            #pragma unroll
            for (int k = 0; k < 8; k++) acb[w*NB + L*8 + k] = ack[k] + excl;
        }
        __syncwarp();

        float ac0 = acb[w*NB], ac255 = acb[w*NB + NB - 1];

        // ---- transfer table (binary search == reference first-match) + loss ----
        double acc = 0.0;
        #pragma unroll
        for (int k = 0; k < 8; k++) {
            int e = L*8 + k;
            float d = dck[k];
            int t;
            if (e == 0)            t = 0;
            else if (e == NB - 1)  t = NB - 1;
            else if (d < ac0 || d > ac255) t = e;   // no j satisfies both conditions
            else {
                // first j in [1,255] with ac[j] >= d  (then ac[j-1] <= d by minimality)
                int lo = 1, hi = NB - 1;
                while (lo < hi) {
                    int mid = (lo + hi) >> 1;
                    if (acb[w*NB + mid] >= d) hi = mid; else lo = mid + 1;
                }
                t = lo;
            }
            unsigned cnt = cntb[w*NB + e];
            double s  = (double)cnt * (double)e + Fb[w*NB + e] * FINV;
            double cT = (double)cnt * (double)t;
            acc += (t <= e) ? (s - cT) : (cT - s);  // sign fixed: v in [e, e+1)
        }
        #pragma unroll
        for (int off = 16; off; off >>= 1) acc += __shfl_down_sync(FULL, acc, off);
        if (L == 0) s_ls[w] = acc;
    }
    __syncthreads();

    if (threadIdx.x == 0) {
        double tot = 0.0;
        #pragma unroll
        for (int r = 0; r < NRC; r++) tot += s_ls[r];
        out[0] = (float)(0.1 * tot / (3.0 * (double)NPIX));
        g_ctr = 0;                                  // reset for next graph replay
    }
}

extern "C" void kernel_launch(void* const* d_in, const int* in_sizes, int n_in,
                              void* d_out, int out_size)
{
    const float4* fa = (const float4*)d_in[0];
    const float4* rb = (const float4*)d_in[1];
    const int4*   ma = (const int4*)d_in[2];
    const int4*   mb = (const int4*)d_in[3];

    cudaFuncSetAttribute(hm_all, cudaFuncAttributeMaxDynamicSharedMemorySize, SMEM1);
    hm_all<<<GRID1, THR1, SMEM1>>>(fa, rb, ma, mb, (float*)d_out);
}